// round 10
// baseline (speedup 1.0000x reference)
#include <cuda_runtime.h>
#include <cuda_fp16.h>
#include <cstdint>

// ---------------------------------------------------------------------------
// QuantizedLinear: y[64,14336] = x[64,8192] @ dequant_int4(w_packed, w_scales)^T + bias
//
// compute_103-portable path: cp.async 7-stage pipeline + mma.sync.m16n8k16
// HMMA, in-register int4->fp16 dequant (exact; scale/bias in fp32 epilogue).
// R9 @103us was per-warp cp.async-issue bound (192 granules x 8cyc = chunk
// time). R10: 512 threads / 16 warps halves per-warp fill issue and doubles
// latency hiding. Warp grid 4 row-groups x 4 token-groups (32 rows x 16 tok).
// ---------------------------------------------------------------------------

#define M_TOK   64
#define K_IN    8192
#define N_OUT   14336
#define ROWS    128                 // out-rows per CTA
#define KC      64                  // K per chunk
#define NCH     (K_IN / KC)         // 128 chunks
#define NSTG    7                   // pipeline stages
#define WSTRIDE 144                 // smem bytes per W row (128 data + 16 pad)
#define XSTRIDE 160                 // smem bytes per x row (128 data + 32 pad)
#define WB      (ROWS * WSTRIDE)    // 18432
#define XB      (M_TOK * XSTRIDE)   // 10240
#define STG_B   (WB + XB)           // 28672
#define SMEM_TOTAL (NSTG * STG_B)   // 200704
#define NTHREADS 512

// x as fp16 half2 words, 4096 words per token, permuted within each 8-word
// group as [0,4,1,5,2,6,3,7] so one LDS.64 yields an mma B fragment {b0,b1}.
__device__ __align__(16) uint32_t g_x16[M_TOK * (K_IN / 2)];

// ---------------------------------------------------------------------------
__device__ __forceinline__ uint32_t smem_u32(const void* p) {
    uint32_t a;
    asm("{ .reg .u64 t; cvta.to.shared.u64 t, %1; cvt.u32.u64 %0, t; }" : "=r"(a) : "l"(p));
    return a;
}
__device__ __forceinline__ void cp16(uint32_t dst, const void* src) {
    asm volatile("cp.async.cg.shared.global [%0], [%1], 16;" :: "r"(dst), "l"(src) : "memory");
}
#define CP_COMMIT() asm volatile("cp.async.commit_group;" ::: "memory")

__device__ __forceinline__ uint32_t lds32(uint32_t a) {
    uint32_t v;
    asm volatile("ld.shared.b32 %0, [%1];" : "=r"(v) : "r"(a));
    return v;
}
__device__ __forceinline__ void lds64(uint32_t& x, uint32_t& yv, uint32_t a) {
    asm volatile("ld.shared.v2.b32 {%0,%1}, [%2];" : "=r"(x), "=r"(yv) : "r"(a));
}

// int32 holding one packed byte (low nibble = even k, high nibble = odd k)
// -> f16x2 {even k, odd k} with exact signed int4 values.
__device__ __forceinline__ uint32_t nib2h(uint32_t w) {
    uint32_t t = (w | (w << 12)) & 0x000F000Fu;   // SHL + LOP3
    t = (t ^ 0x00080008u) | 0x64006400u;          // LOP3: 1024 + (q^8) per half
    uint32_t r;
    asm("sub.rn.f16x2 %0, %1, %2;" : "=r"(r) : "r"(t), "r"(0x64086408u)); // -1032
    return r;
}

__device__ __forceinline__ void mma16816(float* c,
                                         uint32_t a0, uint32_t a1, uint32_t a2, uint32_t a3,
                                         uint32_t b0, uint32_t b1) {
    asm volatile(
        "mma.sync.aligned.m16n8k16.row.col.f32.f16.f16.f32 "
        "{%0,%1,%2,%3}, {%4,%5,%6,%7}, {%8,%9}, {%0,%1,%2,%3};"
        : "+f"(c[0]), "+f"(c[1]), "+f"(c[2]), "+f"(c[3])
        : "r"(a0), "r"(a1), "r"(a2), "r"(a3), "r"(b0), "r"(b1));
}

// ---------------------------------------------------------------------------
// x fp32 -> fp16 pre-kernel with per-8-word pair permutation.
// Output word p of a token row: group q = p>>3, slot u = p&7,
// original word o = q*8 + ((u>>1) | ((u&1)<<2)).
// ---------------------------------------------------------------------------
__global__ void xconv_kernel(const float* __restrict__ x) {
    int i = blockIdx.x * blockDim.x + threadIdx.x;    // 0 .. 262143
    int tok = i >> 12;
    int p = i & 4095;
    int q = p >> 3, u = p & 7;
    int o = (q << 3) | ((u >> 1) | ((u & 1) << 2));
    float2 v = reinterpret_cast<const float2*>(x)[tok * 4096 + o];
    __half2 h = __floats2half2_rn(v.x, v.y);
    g_x16[i] = *reinterpret_cast<uint32_t*>(&h);
}

// ---------------------------------------------------------------------------
// Main kernel: 112 CTAs x 512 threads (16 warps).
// Warp grid: wr = wid&3 (row-group of 32 rows), wt = wid>>2 (token-group of 16).
// Warp computes 32 out-rows x 16 tokens = 2 m-tiles x 2 n-tiles per k-step.
// ---------------------------------------------------------------------------
__global__ void __launch_bounds__(NTHREADS, 1)
qlin_kernel(const int* __restrict__ wp, const float* __restrict__ ws,
            const float* __restrict__ bias, float* __restrict__ y) {
    extern __shared__ char smem[];
    const uint32_t sb = smem_u32(smem);
    const int tid = threadIdx.x;
    const int wid = tid >> 5, lane = tid & 31;
    const int g = lane >> 2, t = lane & 3;            // mma fragment coords
    const int wr = wid & 3, wt = wid >> 2;
    const int row0 = blockIdx.x * ROWS;
    const int* __restrict__ wrow_base = wp + (size_t)row0 * (K_IN / 2);

    float acc[2][2][4];
    #pragma unroll
    for (int mt = 0; mt < 2; ++mt)
        #pragma unroll
        for (int j = 0; j < 2; ++j)
            #pragma unroll
            for (int e = 0; e < 4; ++e) acc[mt][j][e] = 0.0f;

    // ---- fill one stage with chunk c (1536 granules of 16B / 512 threads) ----
    auto fill = [&](int c, int slot) {
        uint32_t wbase = sb + slot * STG_B;
        uint32_t xbase = wbase + WB;
        const int* wsrc = wrow_base + c * 32;
        const uint32_t* xsrc = g_x16 + c * 32;
        #pragma unroll
        for (int it = 0; it < 2; ++it) {
            int id = it * NTHREADS + tid;                   // 0..1023
            int r = id >> 3, gr = id & 7;
            cp16(wbase + r * WSTRIDE + gr * 16, wsrc + (size_t)r * 4096 + gr * 4);
        }
        {
            int tok = tid >> 3, gr = tid & 7;               // 0..511
            cp16(xbase + tok * XSTRIDE + gr * 16, xsrc + tok * 4096 + gr * 4);
        }
    };

    // prologue: chunks 0..NSTG-2 into slots 0..NSTG-2
    #pragma unroll
    for (int c = 0; c < NSTG - 1; ++c) { fill(c, c); CP_COMMIT(); }

    #pragma unroll 1
    for (int i = 0; i < NCH; ++i) {
        asm volatile("cp.async.wait_group %0;" :: "n"(NSTG - 2) : "memory");
        __syncthreads();   // chunk i visible; slot (i-1)%NSTG fully consumed

        int cf = i + NSTG - 1;
        if (cf < NCH) fill(cf, cf % NSTG);
        CP_COMMIT();       // empty group at tail keeps wait_group count aligned

        // ---- consume chunk i ----
        uint32_t wbase = sb + (i % NSTG) * STG_B;
        uint32_t xbase = wbase + WB;
        uint32_t wr0 = wbase + (wr * 32 + g) * WSTRIDE + t * 4;   // m-tile 0
        uint32_t xr0 = xbase + (wt * 16 + g) * XSTRIDE + t * 8;   // n-tile 0

        #pragma unroll
        for (int s = 0; s < 4; ++s) {
            uint32_t a[2][4];
            #pragma unroll
            for (int mt = 0; mt < 2; ++mt) {
                uint32_t base = wr0 + mt * (16 * WSTRIDE) + s * 32;
                a[mt][0] = nib2h(lds32(base));                      // row g,   k 2t..
                a[mt][1] = nib2h(lds32(base + 8 * WSTRIDE));        // row g+8
                a[mt][2] = nib2h(lds32(base + 16));                 // row g,   k 2t+8..
                a[mt][3] = nib2h(lds32(base + 8 * WSTRIDE + 16));   // row g+8
            }
            #pragma unroll
            for (int j = 0; j < 2; ++j) {
                uint32_t b0, b1;
                lds64(b0, b1, xr0 + j * (8 * XSTRIDE) + s * 32);
                mma16816(acc[0][j], a[0][0], a[0][1], a[0][2], a[0][3], b0, b1);
                mma16816(acc[1][j], a[1][0], a[1][1], a[1][2], a[1][3], b0, b1);
            }
        }
    }

    // ---- epilogue: D * scale + bias (32B-sector stores) ----
    #pragma unroll
    for (int mt = 0; mt < 2; ++mt) {
        int r = row0 + wr * 32 + mt * 16 + g;
        float s0 = ws[r],     b0v = bias[r];
        float s1 = ws[r + 8], b1v = bias[r + 8];
        #pragma unroll
        for (int j = 0; j < 2; ++j) {
            int tok = wt * 16 + j * 8 + 2 * t;
            y[(size_t)tok * N_OUT + r]           = acc[mt][j][0] * s0 + b0v;
            y[(size_t)(tok + 1) * N_OUT + r]     = acc[mt][j][1] * s0 + b0v;
            y[(size_t)tok * N_OUT + r + 8]       = acc[mt][j][2] * s1 + b1v;
            y[(size_t)(tok + 1) * N_OUT + r + 8] = acc[mt][j][3] * s1 + b1v;
        }
    }
}

// ---------------------------------------------------------------------------
// Inputs (metadata order): x(f32), w_packed(i32), w_scales(f32), bias(f32)
// ---------------------------------------------------------------------------
extern "C" void kernel_launch(void* const* d_in, const int* in_sizes, int n_in,
                              void* d_out, int out_size) {
    const float* x    = (const float*)d_in[0];
    const int*   wpk  = (const int*)d_in[1];
    const float* wsc  = (const float*)d_in[2];
    const float* bias = (const float*)d_in[3];
    float* y = (float*)d_out;

    cudaFuncSetAttribute(qlin_kernel, cudaFuncAttributeMaxDynamicSharedMemorySize, SMEM_TOTAL);

    xconv_kernel<<<(M_TOK * K_IN / 2) / 256, 256>>>(x);
    qlin_kernel<<<N_OUT / ROWS, NTHREADS, SMEM_TOTAL>>>(wpk, wsc, bias, y);
}

// round 13
// speedup vs baseline: 1.3002x; 1.3002x over previous
#include <cuda_runtime.h>
#include <cuda_fp16.h>
#include <cstdint>

// ---------------------------------------------------------------------------
// QuantizedLinear: y[64,14336] = x[64,8192] @ dequant_int4(w_packed, w_scales)^T + bias
//
// compute_103-portable: cp.async 4-stage pipeline (KC=128) + mma.sync.m16n8k16
// HMMA, in-register int4->fp16 dequant (exact; scale/bias fp32 epilogue).
// R12 (= R11 resubmit after infra failure): 128 CTAs x 112 rows (fills
// 128/148 SMs), KC=128 halves per-chunk overhead, 14 warps (7 row-groups x
// 2 token-groups) hide latency at R9's instruction-redundancy level.
// ---------------------------------------------------------------------------

#define M_TOK   64
#define K_IN    8192
#define N_OUT   14336
#define ROWS    112                 // out-rows per CTA -> 128 CTAs
#define KC      128                 // K per chunk (64 int32 words per row)
#define NCH     (K_IN / KC)         // 64 chunks
#define NSTG    4                   // pipeline stages
#define WSTRIDE 272                 // smem bytes per W row (256 data + 16 pad)
#define XSTRIDE 288                 // smem bytes per x row (256 data + 32 pad)
#define WB      (ROWS * WSTRIDE)    // 30464
#define XB      (M_TOK * XSTRIDE)   // 18432
#define STG_B   (WB + XB)           // 48896
#define SMEM_TOTAL (NSTG * STG_B)   // 195584
#define NTHREADS 448                // 14 warps: 7 row-groups x 2 token-groups
#define NGRAN   ((ROWS + M_TOK) * 16)   // 2816 16B-granules per stage

// x as fp16 half2 words, 4096 words per token, permuted within each 8-word
// group as [0,4,1,5,2,6,3,7] so one LDS.64 yields an mma B fragment {b0,b1}.
__device__ __align__(16) uint32_t g_x16[M_TOK * (K_IN / 2)];

// ---------------------------------------------------------------------------
__device__ __forceinline__ uint32_t smem_u32(const void* p) {
    uint32_t a;
    asm("{ .reg .u64 t; cvta.to.shared.u64 t, %1; cvt.u32.u64 %0, t; }" : "=r"(a) : "l"(p));
    return a;
}
__device__ __forceinline__ void cp16(uint32_t dst, const void* src) {
    asm volatile("cp.async.cg.shared.global [%0], [%1], 16;" :: "r"(dst), "l"(src) : "memory");
}
#define CP_COMMIT() asm volatile("cp.async.commit_group;" ::: "memory")

__device__ __forceinline__ uint32_t lds32(uint32_t a) {
    uint32_t v;
    asm volatile("ld.shared.b32 %0, [%1];" : "=r"(v) : "r"(a));
    return v;
}
__device__ __forceinline__ void lds64(uint32_t& x, uint32_t& yv, uint32_t a) {
    asm volatile("ld.shared.v2.b32 {%0,%1}, [%2];" : "=r"(x), "=r"(yv) : "r"(a));
}

// int32 holding one packed byte (low nibble = even k, high nibble = odd k)
// -> f16x2 {even k, odd k} with exact signed int4 values.
__device__ __forceinline__ uint32_t nib2h(uint32_t w) {
    uint32_t t = (w | (w << 12)) & 0x000F000Fu;   // SHL + LOP3
    t = (t ^ 0x00080008u) | 0x64006400u;          // LOP3: 1024 + (q^8) per half
    uint32_t r;
    asm("sub.rn.f16x2 %0, %1, %2;" : "=r"(r) : "r"(t), "r"(0x64086408u)); // -1032
    return r;
}

__device__ __forceinline__ void mma16816(float* c,
                                         uint32_t a0, uint32_t a1, uint32_t a2, uint32_t a3,
                                         uint32_t b0, uint32_t b1) {
    asm volatile(
        "mma.sync.aligned.m16n8k16.row.col.f32.f16.f16.f32 "
        "{%0,%1,%2,%3}, {%4,%5,%6,%7}, {%8,%9}, {%0,%1,%2,%3};"
        : "+f"(c[0]), "+f"(c[1]), "+f"(c[2]), "+f"(c[3])
        : "r"(a0), "r"(a1), "r"(a2), "r"(a3), "r"(b0), "r"(b1));
}

// ---------------------------------------------------------------------------
// x fp32 -> fp16 pre-kernel with per-8-word pair permutation.
// Output word p of a token row: group q = p>>3, slot u = p&7,
// original word o = q*8 + ((u>>1) | ((u&1)<<2)).
// ---------------------------------------------------------------------------
__global__ void xconv_kernel(const float* __restrict__ x) {
    int i = blockIdx.x * blockDim.x + threadIdx.x;    // 0 .. 262143
    int tok = i >> 12;
    int p = i & 4095;
    int q = p >> 3, u = p & 7;
    int o = (q << 3) | ((u >> 1) | ((u & 1) << 2));
    float2 v = reinterpret_cast<const float2*>(x)[tok * 4096 + o];
    __half2 h = __floats2half2_rn(v.x, v.y);
    g_x16[i] = *reinterpret_cast<uint32_t*>(&h);
}

// ---------------------------------------------------------------------------
// Main kernel: 128 CTAs x 448 threads (14 warps).
// rg = wid % 7 : 16-row group;  tg = wid / 7 : 32-token group.
// Warp = 16 rows x 32 tokens = 1 m-tile x 4 n-tiles per k-step (8 k-steps).
// ---------------------------------------------------------------------------
__global__ void __launch_bounds__(NTHREADS, 1)
qlin_kernel(const int* __restrict__ wp, const float* __restrict__ ws,
            const float* __restrict__ bias, float* __restrict__ y) {
    extern __shared__ char smem[];
    const uint32_t sb = smem_u32(smem);
    const int tid = threadIdx.x;
    const int wid = tid >> 5, lane = tid & 31;
    const int g = lane >> 2, t = lane & 3;            // mma fragment coords
    const int rg = wid % 7, tg = wid / 7;
    const int row0 = blockIdx.x * ROWS;
    const int* __restrict__ wrow_base = wp + (size_t)row0 * (K_IN / 2);

    float acc[4][4];
    #pragma unroll
    for (int j = 0; j < 4; ++j)
        #pragma unroll
        for (int e = 0; e < 4; ++e) acc[j][e] = 0.0f;

    // ---- fill one stage with chunk c (2816 granules of 16B / 448 threads) ----
    auto fill = [&](int c, int slot) {
        uint32_t wbase = sb + slot * STG_B;
        uint32_t xbase = wbase + WB;
        const int* wsrc = wrow_base + c * (KC / 2);          // + row*4096 below
        const uint32_t* xsrc = g_x16 + c * (KC / 2);         // + tok*4096 below
        #pragma unroll
        for (int it = 0; it < 7; ++it) {
            int id = it * NTHREADS + tid;
            if (id < ROWS * 16) {                            // W: 1792 granules
                int r = id >> 4, gr = id & 15;
                cp16(wbase + r * WSTRIDE + gr * 16, wsrc + (size_t)r * 4096 + gr * 4);
            } else if (id < NGRAN) {                         // x: 1024 granules
                int id2 = id - ROWS * 16;
                int tok = id2 >> 4, gr = id2 & 15;
                cp16(xbase + tok * XSTRIDE + gr * 16, xsrc + tok * 4096 + gr * 4);
            }
        }
    };

    // prologue: chunks 0..NSTG-2 into slots 0..NSTG-2
    #pragma unroll
    for (int c = 0; c < NSTG - 1; ++c) { fill(c, c); CP_COMMIT(); }

    #pragma unroll 1
    for (int i = 0; i < NCH; ++i) {
        asm volatile("cp.async.wait_group %0;" :: "n"(NSTG - 2) : "memory");
        __syncthreads();   // chunk i visible; slot (i-1)%NSTG fully consumed

        int cf = i + NSTG - 1;
        if (cf < NCH) fill(cf, cf % NSTG);
        CP_COMMIT();       // empty group at tail keeps wait_group count aligned

        // ---- consume chunk i ----
        uint32_t wbase = sb + (i % NSTG) * STG_B;
        uint32_t xbase = wbase + WB;
        uint32_t wr0 = wbase + (rg * 16 + g) * WSTRIDE + t * 4;
        uint32_t xr0 = xbase + (tg * 32 + g) * XSTRIDE + t * 8;

        #pragma unroll
        for (int s = 0; s < 8; ++s) {
            uint32_t base = wr0 + s * 32;
            uint32_t a0 = nib2h(lds32(base));                      // row g,   k 2t..
            uint32_t a1 = nib2h(lds32(base + 8 * WSTRIDE));        // row g+8
            uint32_t a2 = nib2h(lds32(base + 16));                 // row g,   k 2t+8..
            uint32_t a3 = nib2h(lds32(base + 8 * WSTRIDE + 16));   // row g+8
            #pragma unroll
            for (int j = 0; j < 4; ++j) {
                uint32_t b0, b1;
                lds64(b0, b1, xr0 + j * (8 * XSTRIDE) + s * 32);
                mma16816(acc[j], a0, a1, a2, a3, b0, b1);
            }
        }
    }

    // ---- epilogue: D * scale + bias (32B-sector stores) ----
    {
        int r = row0 + rg * 16 + g;
        float s0 = ws[r],     b0v = bias[r];
        float s1 = ws[r + 8], b1v = bias[r + 8];
        #pragma unroll
        for (int j = 0; j < 4; ++j) {
            int tok = tg * 32 + j * 8 + 2 * t;
            y[(size_t)tok * N_OUT + r]           = acc[j][0] * s0 + b0v;
            y[(size_t)(tok + 1) * N_OUT + r]     = acc[j][1] * s0 + b0v;
            y[(size_t)tok * N_OUT + r + 8]       = acc[j][2] * s1 + b1v;
            y[(size_t)(tok + 1) * N_OUT + r + 8] = acc[j][3] * s1 + b1v;
        }
    }
}

// ---------------------------------------------------------------------------
// Inputs (metadata order): x(f32), w_packed(i32), w_scales(f32), bias(f32)
// ---------------------------------------------------------------------------
extern "C" void kernel_launch(void* const* d_in, const int* in_sizes, int n_in,
                              void* d_out, int out_size) {
    const float* x    = (const float*)d_in[0];
    const int*   wpk  = (const int*)d_in[1];
    const float* wsc  = (const float*)d_in[2];
    const float* bias = (const float*)d_in[3];
    float* y = (float*)d_out;

    cudaFuncSetAttribute(qlin_kernel, cudaFuncAttributeMaxDynamicSharedMemorySize, SMEM_TOTAL);

    xconv_kernel<<<(M_TOK * K_IN / 2) / 256, 256>>>(x);
    qlin_kernel<<<N_OUT / ROWS, NTHREADS, SMEM_TOTAL>>>(wpk, wsc, bias, y);
}

// round 14
// speedup vs baseline: 1.3367x; 1.0281x over previous
#include <cuda_runtime.h>
#include <cuda_fp16.h>
#include <cstdint>

// ---------------------------------------------------------------------------
// QuantizedLinear: y[64,14336] = x[64,8192] @ dequant_int4(w_packed, w_scales)^T + bias
//
// R14: in-CTA K-split. 112 CTAs x 512 threads; warp grid rg(4) x kg(4):
// warp = 32 rows x 64 tokens x 32-k quarter per 128-k chunk. Crossbar/chunk
// drops 214K -> 146K (A read once, B redundancy rg=4) while warps rise to 16
// (kg adds warps with ZERO crossbar cost; only a one-time smem reduction).
// cp.async 4-stage pipeline + mma.sync.m16n8k16, exact in-register int4->fp16
// dequant, fp32 scale/bias epilogue.
// ---------------------------------------------------------------------------

#define M_TOK   64
#define K_IN    8192
#define N_OUT   14336
#define ROWS    128                 // out-rows per CTA -> 112 CTAs
#define KC      128                 // K per chunk (64 int32 words per row)
#define NCH     (K_IN / KC)         // 64 chunks
#define NSTG    4                   // pipeline stages
#define WSTRIDE 272                 // smem bytes per W row (256 data + 16 pad)
#define XSTRIDE 288                 // smem bytes per x row (256 data + 32 pad)
#define WB      (ROWS * WSTRIDE)    // 34816
#define XB      (M_TOK * XSTRIDE)   // 18432
#define STG_B   (WB + XB)           // 53248
#define SMEM_TOTAL (NSTG * STG_B)   // 212992
#define NTHREADS 512                // 16 warps: rg(4) x kg(4)

// x as fp16 half2 words, 4096 words per token, permuted within each 8-word
// group as [0,4,1,5,2,6,3,7] so one LDS.64 yields an mma B fragment {b0,b1}.
__device__ __align__(16) uint32_t g_x16[M_TOK * (K_IN / 2)];

// ---------------------------------------------------------------------------
__device__ __forceinline__ uint32_t smem_u32(const void* p) {
    uint32_t a;
    asm("{ .reg .u64 t; cvta.to.shared.u64 t, %1; cvt.u32.u64 %0, t; }" : "=r"(a) : "l"(p));
    return a;
}
__device__ __forceinline__ void cp16(uint32_t dst, const void* src) {
    asm volatile("cp.async.cg.shared.global [%0], [%1], 16;" :: "r"(dst), "l"(src) : "memory");
}
#define CP_COMMIT() asm volatile("cp.async.commit_group;" ::: "memory")

__device__ __forceinline__ uint32_t lds32(uint32_t a) {
    uint32_t v;
    asm volatile("ld.shared.b32 %0, [%1];" : "=r"(v) : "r"(a));
    return v;
}
__device__ __forceinline__ void lds64(uint32_t& x, uint32_t& yv, uint32_t a) {
    asm volatile("ld.shared.v2.b32 {%0,%1}, [%2];" : "=r"(x), "=r"(yv) : "r"(a));
}
__device__ __forceinline__ float4 lds128f(uint32_t a) {
    float4 v;
    asm volatile("ld.shared.v4.f32 {%0,%1,%2,%3}, [%4];"
                 : "=f"(v.x), "=f"(v.y), "=f"(v.z), "=f"(v.w) : "r"(a));
    return v;
}
__device__ __forceinline__ void sts128f(uint32_t a, float4 v) {
    asm volatile("st.shared.v4.f32 [%0], {%1,%2,%3,%4};"
                 :: "r"(a), "f"(v.x), "f"(v.y), "f"(v.z), "f"(v.w) : "memory");
}

// int32 holding one packed byte (low nibble = even k, high nibble = odd k)
// -> f16x2 {even k, odd k} with exact signed int4 values.
__device__ __forceinline__ uint32_t nib2h(uint32_t w) {
    uint32_t t = (w | (w << 12)) & 0x000F000Fu;   // SHL + LOP3
    t = (t ^ 0x00080008u) | 0x64006400u;          // LOP3: 1024 + (q^8) per half
    uint32_t r;
    asm("sub.rn.f16x2 %0, %1, %2;" : "=r"(r) : "r"(t), "r"(0x64086408u)); // -1032
    return r;
}

__device__ __forceinline__ void mma16816(float* c,
                                         uint32_t a0, uint32_t a1, uint32_t a2, uint32_t a3,
                                         uint32_t b0, uint32_t b1) {
    asm volatile(
        "mma.sync.aligned.m16n8k16.row.col.f32.f16.f16.f32 "
        "{%0,%1,%2,%3}, {%4,%5,%6,%7}, {%8,%9}, {%0,%1,%2,%3};"
        : "+f"(c[0]), "+f"(c[1]), "+f"(c[2]), "+f"(c[3])
        : "r"(a0), "r"(a1), "r"(a2), "r"(a3), "r"(b0), "r"(b1));
}

// ---------------------------------------------------------------------------
// x fp32 -> fp16 pre-kernel with per-8-word pair permutation.
// Output word p of a token row: group q = p>>3, slot u = p&7,
// original word o = q*8 + ((u>>1) | ((u&1)<<2)).
// ---------------------------------------------------------------------------
__global__ void xconv_kernel(const float* __restrict__ x) {
    int i = blockIdx.x * blockDim.x + threadIdx.x;    // 0 .. 262143
    int tok = i >> 12;
    int p = i & 4095;
    int q = p >> 3, u = p & 7;
    int o = (q << 3) | ((u >> 1) | ((u & 1) << 2));
    float2 v = reinterpret_cast<const float2*>(x)[tok * 4096 + o];
    __half2 h = __floats2half2_rn(v.x, v.y);
    g_x16[i] = *reinterpret_cast<uint32_t*>(&h);
}

// ---------------------------------------------------------------------------
// Main kernel: 112 CTAs x 512 threads (16 warps).
// rg = wid&3 : 32-row group (2 m-tiles); kg = wid>>2 : 32-k quarter of chunk.
// Each warp: all 64 tokens (8 n-tiles), 2 k-steps of 16 per chunk.
// ---------------------------------------------------------------------------
__global__ void __launch_bounds__(NTHREADS, 1)
qlin_kernel(const int* __restrict__ wp, const float* __restrict__ ws,
            const float* __restrict__ bias, float* __restrict__ y) {
    extern __shared__ char smem[];
    const uint32_t sb = smem_u32(smem);
    const int tid = threadIdx.x;
    const int wid = tid >> 5, lane = tid & 31;
    const int g = lane >> 2, t = lane & 3;            // mma fragment coords
    const int rg = wid & 3, kg = wid >> 2;
    const int row0 = blockIdx.x * ROWS;
    const int* __restrict__ wrow_base = wp + (size_t)row0 * (K_IN / 2);

    float acc[2][8][4];                               // [m-tile][n-tile][frag]
    #pragma unroll
    for (int mt = 0; mt < 2; ++mt)
        #pragma unroll
        for (int j = 0; j < 8; ++j)
            #pragma unroll
            for (int e = 0; e < 4; ++e) acc[mt][j][e] = 0.0f;

    // ---- fill one stage with chunk c: 3072 granules = 6 x 512 exactly ----
    auto fill = [&](int c, int slot) {
        uint32_t wbase = sb + slot * STG_B;
        uint32_t xbase = wbase + WB;
        const int* wsrc = wrow_base + c * (KC / 2);          // + row*4096 below
        const uint32_t* xsrc = g_x16 + c * (KC / 2);         // + tok*4096 below
        #pragma unroll
        for (int it = 0; it < 6; ++it) {
            int id = it * NTHREADS + tid;
            if (id < ROWS * 16) {                            // W: 2048 granules
                int r = id >> 4, gr = id & 15;
                cp16(wbase + r * WSTRIDE + gr * 16, wsrc + (size_t)r * 4096 + gr * 4);
            } else {                                         // x: 1024 granules
                int id2 = id - ROWS * 16;
                int tok = id2 >> 4, gr = id2 & 15;
                cp16(xbase + tok * XSTRIDE + gr * 16, xsrc + tok * 4096 + gr * 4);
            }
        }
    };

    // prologue: chunks 0..NSTG-2 into slots 0..NSTG-2
    #pragma unroll
    for (int c = 0; c < NSTG - 1; ++c) { fill(c, c); CP_COMMIT(); }

    #pragma unroll 1
    for (int i = 0; i < NCH; ++i) {
        asm volatile("cp.async.wait_group %0;" :: "n"(NSTG - 2) : "memory");
        __syncthreads();   // chunk i visible; slot (i-1)%NSTG fully consumed

        int cf = i + NSTG - 1;
        if (cf < NCH) fill(cf, cf % NSTG);
        CP_COMMIT();       // empty group at tail keeps wait_group count aligned

        // ---- consume chunk i: this warp's 32-k quarter (byte offset kg*64) ----
        uint32_t wbase = sb + (i % NSTG) * STG_B;
        uint32_t xbase = wbase + WB;
        uint32_t wr0 = wbase + (rg * 32 + g) * WSTRIDE + t * 4 + kg * 64;
        uint32_t xr0 = xbase + g * XSTRIDE + t * 8 + kg * 64;

        #pragma unroll
        for (int s = 0; s < 2; ++s) {
            uint32_t a[2][4];
            #pragma unroll
            for (int mt = 0; mt < 2; ++mt) {
                uint32_t base = wr0 + mt * (16 * WSTRIDE) + s * 32;
                a[mt][0] = nib2h(lds32(base));                      // row g,   k 2t..
                a[mt][1] = nib2h(lds32(base + 8 * WSTRIDE));        // row g+8
                a[mt][2] = nib2h(lds32(base + 16));                 // row g,   k 2t+8..
                a[mt][3] = nib2h(lds32(base + 8 * WSTRIDE + 16));   // row g+8
            }
            #pragma unroll
            for (int j = 0; j < 8; ++j) {
                uint32_t b0, b1;
                lds64(b0, b1, xr0 + j * (8 * XSTRIDE) + s * 32);
                mma16816(acc[0][j], a[0][0], a[0][1], a[0][2], a[0][3], b0, b1);
                mma16816(acc[1][j], a[1][0], a[1][1], a[1][2], a[1][3], b0, b1);
            }
        }
    }

    // ---- K-split reduction: all warps dump partials, kg==0 warps sum ----
    __syncthreads();                       // pipeline done; smem reusable
    uint32_t rb = sb + wid * 8192 + lane * 16;
    {
        const float4* af = reinterpret_cast<const float4*>(&acc[0][0][0]);
        #pragma unroll
        for (int i = 0; i < 16; ++i) sts128f(rb + i * 512, af[i]);
    }
    __syncthreads();

    if (kg == 0) {
        float4* af = reinterpret_cast<float4*>(&acc[0][0][0]);
        #pragma unroll
        for (int i = 0; i < 16; ++i) {
            float4 p1 = lds128f(rb + 4 * 8192 + i * 512);
            float4 p2 = lds128f(rb + 8 * 8192 + i * 512);
            float4 p3 = lds128f(rb + 12 * 8192 + i * 512);
            af[i].x += p1.x + p2.x + p3.x;
            af[i].y += p1.y + p2.y + p3.y;
            af[i].z += p1.z + p2.z + p3.z;
            af[i].w += p1.w + p2.w + p3.w;
        }

        // ---- epilogue: D * scale + bias (32B-sector stores) ----
        #pragma unroll
        for (int mt = 0; mt < 2; ++mt) {
            int r = row0 + rg * 32 + mt * 16 + g;
            float s0 = ws[r],     b0v = bias[r];
            float s1 = ws[r + 8], b1v = bias[r + 8];
            #pragma unroll
            for (int j = 0; j < 8; ++j) {
                int tok = j * 8 + 2 * t;
                y[(size_t)tok * N_OUT + r]           = acc[mt][j][0] * s0 + b0v;
                y[(size_t)(tok + 1) * N_OUT + r]     = acc[mt][j][1] * s0 + b0v;
                y[(size_t)tok * N_OUT + r + 8]       = acc[mt][j][2] * s1 + b1v;
                y[(size_t)(tok + 1) * N_OUT + r + 8] = acc[mt][j][3] * s1 + b1v;
            }
        }
    }
}

// ---------------------------------------------------------------------------
// Inputs (metadata order): x(f32), w_packed(i32), w_scales(f32), bias(f32)
// ---------------------------------------------------------------------------
extern "C" void kernel_launch(void* const* d_in, const int* in_sizes, int n_in,
                              void* d_out, int out_size) {
    const float* x    = (const float*)d_in[0];
    const int*   wpk  = (const int*)d_in[1];
    const float* wsc  = (const float*)d_in[2];
    const float* bias = (const float*)d_in[3];
    float* y = (float*)d_out;

    cudaFuncSetAttribute(qlin_kernel, cudaFuncAttributeMaxDynamicSharedMemorySize, SMEM_TOTAL);

    xconv_kernel<<<(M_TOK * K_IN / 2) / 256, 256>>>(x);
    qlin_kernel<<<N_OUT / ROWS, NTHREADS, SMEM_TOTAL>>>(wpk, wsc, bias, y);
}